// round 12
// baseline (speedup 1.0000x reference)
#include <cuda_runtime.h>
#include <cstdint>

// Morton encode permutation, x shape (B=8, C=64, 256, 256) fp32.
// out[plane][morton(i,j)] = x[plane][i][j].
//
// Tile = 32 rows x 256 cols (32KB): input side contiguous 32KB, output side
// 4 contiguous 8KB chunks.
// Phase 1: cp.async.cg 16B global->smem (no register staging).
// Phase 2: per (t): 2x LDS.128 (rows i, i+1, 4 cols) -> 2 output float4s,
//          warp writes 1KB contiguous STG.128.

#define RS 260  // smem row stride in floats (1040B = 65*16B, 16B aligned)

__global__ void __launch_bounds__(256)
morton_smem2_kernel(const float4* __restrict__ in4, float4* __restrict__ out4)
{
    __shared__ float sm[32 * RS];

    unsigned tid = threadIdx.x;
    unsigned b = blockIdx.x;
    unsigned plane = b >> 3;
    unsigned strip = b & 7u;            // rows [strip*32, strip*32+32)

    // ---- Phase 1: contiguous 32KB -> smem via cp.async ----
    const float4* src = in4 + ((size_t)plane << 14) + ((size_t)strip << 11);
#pragma unroll
    for (int k = 0; k < 8; k++) {
        unsigned g = (unsigned)k * 256u + tid;      // float4 index in tile
        unsigned row = g >> 6;
        unsigned c4  = g & 63u;
        unsigned long long sa =
            __cvta_generic_to_shared(&sm[row * RS + c4 * 4]);
        asm volatile("cp.async.cg.shared.global [%0], [%1], 16;\n"
                     :: "l"(sa), "l"(src + g));
    }
    asm volatile("cp.async.commit_group;\ncp.async.wait_group 0;\n" ::: "memory");
    __syncthreads();

    // ---- Phase 2: morton shuffle out of smem ----
    // strip base: i5,i6,i7 -> om bits 9,11,13 (om = morton>>2, float4 units)
    unsigned tb = ((strip & 1u) << 9) | (((strip >> 1) & 1u) << 11)
                | (((strip >> 2) & 1u) << 13);
    float4* dst = out4 + ((size_t)plane << 14) + tb;

#pragma unroll
    for (int k = 0; k < 4; k++) {
        unsigned t = (unsigned)k * 256u + tid;      // handles om {2t, 2t+1}
        // om bits: 0=j1(sel) 1=i1 2=j2 3=i2 4=j3 5=i3 6=j4 7=i4 8=j5 10=j6 12=j7
        // t bits 0..7 -> om bits 1..8; t8 -> om10; t9 -> om12
        unsigned i = ((t & 1u) << 1) | (((t >> 2) & 1u) << 2)
                   | (((t >> 4) & 1u) << 3) | (((t >> 6) & 1u) << 4);
        unsigned j4grp = ((t >> 1) & 1u) | (((t >> 3) & 1u) << 1)
                       | (((t >> 5) & 1u) << 2) | (((t >> 7) & 1u) << 3)
                       | (((t >> 8) & 1u) << 4) | (((t >> 9) & 1u) << 5);

        const float* base = &sm[i * RS + j4grp * 4];
        float4 q0 = *reinterpret_cast<const float4*>(base);        // row i
        float4 q1 = *reinterpret_cast<const float4*>(base + RS);   // row i+1

        unsigned oidx = ((t & 0xFFu) << 1) | (((t >> 8) & 1u) << 10)
                      | (((t >> 9) & 1u) << 12);
        __stcs(dst + oidx,     make_float4(q0.x, q0.y, q1.x, q1.y));
        __stcs(dst + oidx + 1, make_float4(q0.z, q0.w, q1.z, q1.w));
    }
}

extern "C" void kernel_launch(void* const* d_in, const int* in_sizes, int n_in,
                              void* d_out, int out_size) {
    const float4* in4 = (const float4*)d_in[0];
    float4* out4 = (float4*)d_out;

    int nblocks = out_size / 8192;   // one 32x256 tile per block
    morton_smem2_kernel<<<nblocks, 256>>>(in4, out4);
}

// round 15
// speedup vs baseline: 1.0410x; 1.0410x over previous
#include <cuda_runtime.h>
#include <cstdint>

// Morton encode permutation, x shape (B=8, C=64, 256, 256) fp32.
// out[plane][morton(i,j)] = x[plane][i][j].
//
// R2 structure (measured best, 43.2us) made PERSISTENT:
//   grid = 820 resident blocks (single wave at 6 CTA/SM), grid-stride over
//   4096 tiles -> no wave transitions, no launch tail.
// Tile = 32 rows x 256 cols (32KB): input contiguous 32KB; output = 4
// contiguous 8KB chunks.
// Phase 1: 8x LDG.128 coalesced -> STS.128.
// Phase 2: 4x LDS.64 pairs -> streaming STG.128.

#define RS 260  // smem row stride in floats (1040B = 65*16B, 16B aligned)

static __device__ __forceinline__ unsigned ceb(unsigned v) {
    v &= 0x55555555u;
    v = (v | (v >> 1)) & 0x33333333u;
    v = (v | (v >> 2)) & 0x0F0F0F0Fu;
    v = (v | (v >> 4)) & 0x00FF00FFu;
    v = (v | (v >> 8)) & 0x0000FFFFu;
    return v;
}

__global__ void __launch_bounds__(256)
morton_pers_kernel(const float4* __restrict__ in4, float4* __restrict__ out4,
                   int ntiles)
{
    __shared__ float sm[32 * RS];
    unsigned tid = threadIdx.x;

    for (unsigned b = blockIdx.x; b < (unsigned)ntiles; b += gridDim.x) {
        unsigned plane = b >> 3;
        unsigned strip = b & 7u;            // rows [strip*32, strip*32+32)

        // ---- Phase 1: contiguous 32KB read -> smem ----
        const float4* src = in4 + ((size_t)plane << 14) + ((size_t)strip << 11);
        float4 r[8];
#pragma unroll
        for (int k = 0; k < 8; k++)
            r[k] = __ldcs(src + k * 256 + tid);   // coalesced, MLP=8

#pragma unroll
        for (int k = 0; k < 8; k++) {
            unsigned v = (unsigned)k * 256u + tid;
            unsigned row = v >> 6;
            unsigned c4  = v & 63u;
            *reinterpret_cast<float4*>(&sm[row * RS + c4 * 4]) = r[k];
        }
        __syncthreads();

        // ---- Phase 2: morton-ordered write, 4 contiguous 8KB chunks ----
        unsigned tb = ((strip & 1u) << 9) | (((strip >> 1) & 1u) << 11)
                    | (((strip >> 2) & 1u) << 13);
        float4* dst = out4 + ((size_t)plane << 14) + tb;

#pragma unroll
        for (int k = 0; k < 8; k++) {
            unsigned w = (unsigned)k * 256u + tid;   // out float4 within tile
            unsigned chunk = w >> 9;                 // 8KB chunk (j6,j7)
            unsigned tt = w & 511u;

            unsigned j = (ceb(tt) << 1) | ((chunk & 1u) << 6) | ((chunk >> 1) << 7);
            unsigned i = ceb(tt >> 1) << 1;

            float2 lo = *reinterpret_cast<const float2*>(&sm[i * RS + j]);
            float2 hi = *reinterpret_cast<const float2*>(&sm[(i + 1) * RS + j]);

            unsigned oidx = ((chunk & 1u) << 10) | ((chunk >> 1) << 12) | tt;
            __stcs(dst + oidx, make_float4(lo.x, lo.y, hi.x, hi.y));
        }
        __syncthreads();   // protect smem before next tile's phase 1
    }
}

extern "C" void kernel_launch(void* const* d_in, const int* in_sizes, int n_in,
                              void* d_out, int out_size) {
    const float4* in4 = (const float4*)d_in[0];
    float4* out4 = (float4*)d_out;

    int ntiles = out_size / 8192;        // 4096 tiles of 32x256
    int grid = 820;                      // single resident wave (<=888 @ 6/SM)
    if (grid > ntiles) grid = ntiles;
    morton_pers_kernel<<<grid, 256>>>(in4, out4, ntiles);
}

// round 17
// speedup vs baseline: 1.1421x; 1.0970x over previous
#include <cuda_runtime.h>
#include <cstdint>

// Morton encode permutation, x shape (B=8, C=64, 256, 256) fp32.
// out[plane][morton(i,j)] = x[plane][i][j].
//
// Persistent + SOFTWARE-PIPELINED: while phase-2 writes tile b (smem->gmem),
// the 8 LDG.128 for tile b+1 are already in flight into a second register
// set. Keeps read and write DRAM streams concurrently active from every CTA
// and hides load latency under the store phase (removes the load->barrier
// exposure of the two-phase structure).
//
// Tile = 32 rows x 256 cols (32KB): input contiguous 32KB; output = 4
// contiguous 8KB chunks. Each block owns a contiguous tile range.

#define RS 260  // smem row stride in floats (1040B = 65*16B, 16B aligned)

static __device__ __forceinline__ unsigned ceb(unsigned v) {
    v &= 0x55555555u;
    v = (v | (v >> 1)) & 0x33333333u;
    v = (v | (v >> 2)) & 0x0F0F0F0Fu;
    v = (v | (v >> 4)) & 0x00FF00FFu;
    v = (v | (v >> 8)) & 0x0000FFFFu;
    return v;
}

__global__ void __launch_bounds__(256)
morton_pipe_kernel(const float4* __restrict__ in4, float4* __restrict__ out4,
                   int ntiles)
{
    __shared__ float sm[32 * RS];
    unsigned tid = threadIdx.x;

    // Contiguous tile range for this block.
    unsigned nb  = gridDim.x;
    unsigned per = (unsigned)ntiles / nb;
    unsigned rem = (unsigned)ntiles % nb;
    unsigned bx  = blockIdx.x;
    unsigned b0  = bx * per + (bx < rem ? bx : rem);
    unsigned cnt = per + (bx < rem ? 1u : 0u);
    if (cnt == 0) return;

    float4 r[8];
    // Prefetch first tile.
    {
        unsigned b = b0;
        const float4* src = in4 + ((size_t)(b >> 3) << 14) + ((size_t)(b & 7u) << 11);
#pragma unroll
        for (int k = 0; k < 8; k++)
            r[k] = __ldcs(src + k * 256 + tid);
    }

    for (unsigned t = 0; t < cnt; t++) {
        unsigned b = b0 + t;
        unsigned strip = b & 7u;

        // ---- stage current tile's data into smem ----
#pragma unroll
        for (int k = 0; k < 8; k++) {
            unsigned v = (unsigned)k * 256u + tid;
            *reinterpret_cast<float4*>(&sm[(v >> 6) * RS + (v & 63u) * 4]) = r[k];
        }
        __syncthreads();

        // ---- issue next tile's loads NOW (latency hides under phase 2) ----
        float4 r2[8];
        bool more = (t + 1 < cnt);
        if (more) {
            unsigned bn = b + 1;
            const float4* src2 =
                in4 + ((size_t)(bn >> 3) << 14) + ((size_t)(bn & 7u) << 11);
#pragma unroll
            for (int k = 0; k < 8; k++)
                r2[k] = __ldcs(src2 + k * 256 + tid);
        }

        // ---- phase 2: morton-ordered write, 4 contiguous 8KB chunks ----
        unsigned tb = ((strip & 1u) << 9) | (((strip >> 1) & 1u) << 11)
                    | (((strip >> 2) & 1u) << 13);
        float4* dst = out4 + ((size_t)(b >> 3) << 14) + tb;

#pragma unroll
        for (int k = 0; k < 8; k++) {
            unsigned w = (unsigned)k * 256u + tid;
            unsigned chunk = w >> 9;
            unsigned tt = w & 511u;

            unsigned j = (ceb(tt) << 1) | ((chunk & 1u) << 6) | ((chunk >> 1) << 7);
            unsigned i = ceb(tt >> 1) << 1;

            float2 lo = *reinterpret_cast<const float2*>(&sm[i * RS + j]);
            float2 hi = *reinterpret_cast<const float2*>(&sm[(i + 1) * RS + j]);

            unsigned oidx = ((chunk & 1u) << 10) | ((chunk >> 1) << 12) | tt;
            __stcs(dst + oidx, make_float4(lo.x, lo.y, hi.x, hi.y));
        }
        __syncthreads();   // smem free before next STS

        if (more) {
#pragma unroll
            for (int k = 0; k < 8; k++) r[k] = r2[k];
        }
    }
}

extern "C" void kernel_launch(void* const* d_in, const int* in_sizes, int n_in,
                              void* d_out, int out_size) {
    const float4* in4 = (const float4*)d_in[0];
    float4* out4 = (float4*)d_out;

    int ntiles = out_size / 8192;        // 4096 tiles of 32x256
    int grid = 888;                      // 148 SMs x 6 CTAs (smem-limited), 1 wave
    if (grid > ntiles) grid = ntiles;
    morton_pipe_kernel<<<grid, 256>>>(in4, out4, ntiles);
}